// round 15
// baseline (speedup 1.0000x reference)
#include <cuda_runtime.h>
#include <cuda_fp16.h>
#include <math.h>
#include <stdint.h>

// ---------------- problem constants ----------------
#define B_SZ   2
#define L_SZ   2048
#define DM_SZ  1024
#define DS_SZ  64
#define DI_SZ  2048
#define E_SZ   4096              // 2*DI
#define T_SZ   (B_SZ * L_SZ)     // 4096 tokens
#define CH     128               // scan chunk length
#define NC     (L_SZ / CH)       // 16 chunks

// ---------------- scratch (static device memory; no allocations) ----------------
__device__ __align__(1024) float g_xz  [(size_t)T_SZ * E_SZ];
__device__ __align__(1024) float g_ssm [(size_t)T_SZ * 128];
__device__ __align__(1024) float g_abar[(size_t)T_SZ * DS_SZ];
__device__ __align__(1024) float g_bd  [(size_t)T_SZ * DS_SZ];   // B * dt
__device__ __align__(1024) float g_pend[(size_t)B_SZ * NC * DS_SZ];
// hend/hinit layout: [b][k][s][d]  (d contiguous)
__device__ __align__(1024) float g_hend [(size_t)B_SZ * NC * DS_SZ * DI_SZ];
__device__ __align__(1024) float g_hinit[(size_t)B_SZ * NC * DS_SZ * DI_SZ];

// fp16 split planes: [R][2K] = [hi(0:K) | lo(K:2K)]
__device__ __align__(1024) __half g_x2   [(size_t)T_SZ * 2 * DM_SZ];
__device__ __align__(1024) __half g_Win2 [(size_t)E_SZ * 2 * DM_SZ];
__device__ __align__(1024) __half g_xc2  [(size_t)T_SZ * 2 * DI_SZ];
__device__ __align__(1024) __half g_Wx2  [(size_t)128 * 2 * DI_SZ];
__device__ __align__(1024) __half g_y2   [(size_t)T_SZ * 2 * DI_SZ];
__device__ __align__(1024) __half g_Wout2[(size_t)DM_SZ * 2 * DI_SZ];

// ---------------- small PTX helpers ----------------
typedef unsigned long long u64;

__device__ __forceinline__ uint32_t smem_u32(const void* p) {
    uint32_t a;
    asm("{ .reg .u64 t; cvta.to.shared.u64 t, %1; cvt.u32.u64 %0, t; }" : "=r"(a) : "l"(p));
    return a;
}
__device__ __forceinline__ void cp16(uint32_t dst, const void* src) {
    asm volatile("cp.async.cg.shared.global [%0], [%1], 16;" :: "r"(dst), "l"(src));
}
__device__ __forceinline__ void ldm_x4(uint32_t* r, uint32_t addr) {
    asm volatile("ldmatrix.sync.aligned.m8n8.x4.shared.b16 {%0,%1,%2,%3}, [%4];"
                 : "=r"(r[0]), "=r"(r[1]), "=r"(r[2]), "=r"(r[3]) : "r"(addr));
}
__device__ __forceinline__ void mma_f16(float* c, const uint32_t* a, const uint32_t* b) {
    asm volatile("mma.sync.aligned.m16n8k16.row.col.f32.f16.f16.f32 "
                 "{%0,%1,%2,%3}, {%4,%5,%6,%7}, {%8,%9}, {%0,%1,%2,%3};"
                 : "+f"(c[0]), "+f"(c[1]), "+f"(c[2]), "+f"(c[3])
                 : "r"(a[0]), "r"(a[1]), "r"(a[2]), "r"(a[3]), "r"(b[0]), "r"(b[1]));
}
// packed f32x2 (Blackwell sm_100 base ISA)
__device__ __forceinline__ u64 x2mul(u64 a, u64 b) {
    u64 d; asm("mul.rn.f32x2 %0, %1, %2;" : "=l"(d) : "l"(a), "l"(b)); return d;
}
__device__ __forceinline__ u64 x2fma(u64 a, u64 b, u64 c) {
    u64 d; asm("fma.rn.f32x2 %0, %1, %2, %3;" : "=l"(d) : "l"(a), "l"(b), "l"(c)); return d;
}
__device__ __forceinline__ u64 x2add(u64 a, u64 b) {
    u64 d; asm("add.rn.f32x2 %0, %1, %2;" : "=l"(d) : "l"(a), "l"(b)); return d;
}
__device__ __forceinline__ u64 x2pack(float v) {
    u64 d; asm("mov.b64 %0, {%1, %1};" : "=l"(d) : "f"(v)); return d;
}
__device__ __forceinline__ u64 x2pack2(float a, float b) {
    u64 d; asm("mov.b64 %0, {%1, %2};" : "=l"(d) : "f"(a), "f"(b)); return d;
}
__device__ __forceinline__ float2 x2unpack(u64 v) {
    float2 r; asm("mov.b64 {%0, %1}, %2;" : "=f"(r.x), "=f"(r.y) : "l"(v)); return r;
}

// ================= fp16 2-term split TN GEMM via mma.sync =================
// C[M,N] = A[M,K].B[N,K]^T ; A,B are fp16 split planes [R][2K] = [hi|lo].
// Effective K' = 2K via term map: A [Ah|Al], B [Bh|Bh].
template <int BM, int BN, int WM, int WN, int NST>
__global__ void __launch_bounds__((BM / WM) * (BN / WN) * 32)
gemm_mma(const __half* __restrict__ A,
         const __half* __restrict__ B,
         float* __restrict__ C, int K, int N)
{
    constexpr int NTHR = (BM / WM) * (BN / WN) * 32;
    constexpr int ROWS = BM + BN;
    constexpr int MI = WM / 16;
    constexpr int NI = WN / 8;

    __shared__ __align__(128) __half smbuf[NST][ROWS][32];
    const uint32_t smb = smem_u32(smbuf);

    const int tid = threadIdx.x;
    const int wid = tid >> 5;
    const int lane = tid & 31;
    const int lda = 2 * K;
    const int m0 = blockIdx.y * BM;
    const int n0 = blockIdx.x * BN;
    const int tpt = K / 32;
    const int NKT = 2 * tpt;

    const int wm0 = (wid % (BM / WM)) * WM;
    const int wn0 = (wid / (BM / WM)) * WN;

    const int a_r = lane & 15;
    const int a_j = lane >> 4;
    const int b_r = (lane & 7) + 8 * (lane >> 4);
    const int b_j = (lane >> 3) & 1;

    float acc[MI][NI][4];
#pragma unroll
    for (int i = 0; i < MI; i++)
#pragma unroll
        for (int j = 0; j < NI; j++)
#pragma unroll
            for (int q = 0; q < 4; q++) acc[i][j][q] = 0.f;

    auto fill = [&](int s, int kt) {
        const int term = kt / tpt, within = kt % tpt;
        const int aoff = ((term == 1) ? K : 0) + within * 32;
        const int boff = within * 32;
        const uint32_t stb = smb + s * (ROWS * 64);
#pragma unroll
        for (int t = 0; t < (ROWS * 4) / NTHR; t++) {
            const int q = tid + t * NTHR;
            const int r = q >> 2, c = q & 3;
            const uint32_t dst = stb + r * 64 + ((c ^ ((r >> 1) & 3)) * 16);
            const __half* src = (r < BM)
                ? A + (size_t)(m0 + r) * lda + aoff + c * 8
                : B + (size_t)(n0 + (r - BM)) * lda + boff + c * 8;
            cp16(dst, src);
        }
    };

#pragma unroll
    for (int s = 0; s < NST - 1; s++) {
        fill(s, s);
        asm volatile("cp.async.commit_group;" ::: "memory");
    }

    for (int kt = 0; kt < NKT; kt++) {
        asm volatile("cp.async.wait_group %0;" :: "n"(NST - 2) : "memory");
        __syncthreads();

        const int s = kt % NST;
        const uint32_t Abase = smb + s * (ROWS * 64);
        const uint32_t Bbase = Abase + BM * 64;

#pragma unroll
        for (int kk = 0; kk < 2; kk++) {
            const int ch0 = kk * 2;
            uint32_t af[MI][4];
#pragma unroll
            for (int mi = 0; mi < MI; mi++) {
                const int row = wm0 + mi * 16 + a_r;
                const int chunk = ch0 + a_j;
                ldm_x4(af[mi], Abase + row * 64 + ((chunk ^ ((row >> 1) & 3)) * 16));
            }
            uint32_t bf[NI][2];
#pragma unroll
            for (int np = 0; np < NI / 2; np++) {
                const int row = wn0 + np * 16 + b_r;
                const int chunk = ch0 + b_j;
                uint32_t r4[4];
                ldm_x4(r4, Bbase + row * 64 + ((chunk ^ ((row >> 1) & 3)) * 16));
                bf[2 * np][0] = r4[0]; bf[2 * np][1] = r4[1];
                bf[2 * np + 1][0] = r4[2]; bf[2 * np + 1][1] = r4[3];
            }
#pragma unroll
            for (int mi = 0; mi < MI; mi++)
#pragma unroll
                for (int ni = 0; ni < NI; ni++)
                    mma_f16(acc[mi][ni], af[mi], bf[ni]);
        }

        if (kt + NST - 1 < NKT) fill((kt + NST - 1) % NST, kt + NST - 1);
        asm volatile("cp.async.commit_group;" ::: "memory");
    }

#pragma unroll
    for (int mi = 0; mi < MI; mi++) {
        const int row = m0 + wm0 + mi * 16 + (lane >> 2);
#pragma unroll
        for (int ni = 0; ni < NI; ni++) {
            const int col = n0 + wn0 + ni * 8 + (lane & 3) * 2;
            float2 v0 = make_float2(acc[mi][ni][0], acc[mi][ni][1]);
            float2 v1 = make_float2(acc[mi][ni][2], acc[mi][ni][3]);
            *(float2*)&C[(size_t)row * N + col] = v0;
            *(float2*)&C[(size_t)(row + 8) * N + col] = v1;
        }
    }
}

// ================= fp32 -> (hi|lo) fp16 split, half2 stores ==================
__global__ void split_f16_kernel(const float* __restrict__ in,
                                 __half* __restrict__ out,
                                 int Kc, size_t total)
{
    const size_t i = ((size_t)blockIdx.x * blockDim.x + threadIdx.x);
    if (i * 4 >= total) return;
    const int k4 = Kc >> 2;
    const size_t row = i / k4;
    const int col = (int)(i % k4) * 4;
    const float4 v = *(const float4*)&in[row * Kc + col];
    __half* oh = out + row * (size_t)(2 * Kc) + col;
    __half* ol = oh + Kc;
    float f[4] = {v.x, v.y, v.z, v.w};
    float lo[4];
    __half h[4];
#pragma unroll
    for (int j = 0; j < 4; j++) {
        h[j] = __float2half_rn(f[j]);
        lo[j] = f[j] - __half2float(h[j]);
    }
    *(__half2*)(oh)     = __halves2half2(h[0], h[1]);
    *(__half2*)(oh + 2) = __halves2half2(h[2], h[3]);
    *(__half2*)(ol)     = __floats2half2_rn(lo[0], lo[1]);
    *(__half2*)(ol + 2) = __floats2half2_rn(lo[2], lo[3]);
}

// -- depthwise causal conv (k=4) + bias + SiLU, 2 ch/thread, f16-split only ---
__global__ void conv_silu_split_kernel(const float* __restrict__ xz,
                                       const float* __restrict__ cw,
                                       const float* __restrict__ cb,
                                       __half* __restrict__ xc2)
{
    const int idx = blockIdx.x * blockDim.x + threadIdx.x;   // over T*DI/2
    if (idx >= T_SZ * DI_SZ / 2) return;
    const int dh = idx & (DI_SZ / 2 - 1);
    const int d = dh * 2;
    const int t = idx / (DI_SZ / 2);
    const int l = t & (L_SZ - 1);

    const float2 bias = ((const float2*)cb)[dh];
    const float4 w0 = ((const float4*)cw)[d];       // taps of channel d
    const float4 w1 = ((const float4*)cw)[d + 1];   // taps of channel d+1
    const float wa[4] = {w0.x, w0.y, w0.z, w0.w};
    const float wb[4] = {w1.x, w1.y, w1.z, w1.w};

    float ax = bias.x, ay = bias.y;
#pragma unroll
    for (int k = 0; k < 4; k++) {
        if (l - 3 + k >= 0) {
            const float2 xv = *(const float2*)&xz[(size_t)(t - 3 + k) * E_SZ + d];
            ax = fmaf(xv.x, wa[k], ax);
            ay = fmaf(xv.y, wb[k], ay);
        }
    }
    const float vx = ax / (1.f + __expf(-ax));
    const float vy = ay / (1.f + __expf(-ay));

    const __half hx = __float2half_rn(vx);
    const __half hy = __float2half_rn(vy);
    __half* oh = xc2 + (size_t)t * (2 * DI_SZ) + d;
    *(__half2*)(oh) = __halves2half2(hx, hy);
    *(__half2*)(oh + DI_SZ) = __floats2half2_rn(vx - __half2float(hx),
                                                vy - __half2float(hy));
}

// ------- dt GEMV (from xc2 hi+lo) + softplus + abar + bd = B*dt --------------
__global__ __launch_bounds__(128) void dt_abar_kernel(const __half* __restrict__ xc2,
                                                      const float* __restrict__ Wx,
                                                      const float* __restrict__ A_log,
                                                      const float* __restrict__ ssm,
                                                      float* __restrict__ abar,
                                                      float* __restrict__ bd)
{
    const int t = blockIdx.x;
    const int tid = threadIdx.x;
    const float* wdt = Wx + (size_t)128 * DI_SZ;
    const __half* xh = xc2 + (size_t)t * (2 * DI_SZ);
    const __half* xl = xh + DI_SZ;

    float v = 0.f;
#pragma unroll
    for (int i = 0; i < DI_SZ / 128; i++) {
        const int q = tid + i * 128;
        const float xv = __half2float(xh[q]) + __half2float(xl[q]);
        v = fmaf(xv, wdt[q], v);
    }

#pragma unroll
    for (int o = 16; o > 0; o >>= 1) v += __shfl_xor_sync(0xffffffffu, v, o);

    __shared__ float sred[4];
    __shared__ float sdot;
    if ((tid & 31) == 0) sred[tid >> 5] = v;
    __syncthreads();
    if (tid == 0) sdot = sred[0] + sred[1] + sred[2] + sred[3];
    __syncthreads();

    const float dot = sdot;
    const float dt = (dot > 20.f) ? dot : log1pf(__expf(dot));
    if (tid < DS_SZ) {
        abar[(size_t)t * DS_SZ + tid] = __expf(-__expf(A_log[tid]) * dt);
        bd[(size_t)t * DS_SZ + tid] = ssm[(size_t)t * 128 + tid] * dt;
    }
}

// ---------------- chunk-end decay products (Pend only) -----------------------
__global__ void pend_kernel(const float* __restrict__ abar, float* __restrict__ pend)
{
    const int idx = blockIdx.x * blockDim.x + threadIdx.x;   // (b*NC+k)*64+s
    if (idx >= B_SZ * NC * DS_SZ) return;
    const int b = idx / (NC * DS_SZ);
    const int k = (idx / DS_SZ) % NC;
    const int s = idx & (DS_SZ - 1);
    const int tbase = b * L_SZ + k * CH;

    float p = 1.f;
    for (int i = 0; i < CH; i++)
        p *= abar[(size_t)(tbase + i) * DS_SZ + s];
    pend[idx] = p;
}

// ---------------- pass1: chunk-local scan -> hend only -----------------------
// 1 thread = 1 channel, 64 states in registers (32 packed f32x2).
#define SC_TS 16

__global__ __launch_bounds__(128, 4) void scan_pass1(const float* __restrict__ bd,
                                                     const __half* __restrict__ xc2,
                                                     const float* __restrict__ abar,
                                                     float* __restrict__ hend)
{
    __shared__ __align__(16) float sAb[SC_TS][DS_SZ];
    __shared__ __align__(16) float sBd[SC_TS][DS_SZ];
    __shared__ float sx[SC_TS][128];

    const int tid = threadIdx.x;
    const int bid = blockIdx.x;                 // B * (NC-1) * (DI/128)
    const int b  = bid / ((NC - 1) * (DI_SZ / 128));
    const int r  = bid % ((NC - 1) * (DI_SZ / 128));
    const int k  = r / (DI_SZ / 128);
    const int d0 = (r % (DI_SZ / 128)) * 128;
    const int rbase = b * L_SZ + k * CH;
    const int dg = d0 + tid;

    u64 h[32];
#pragma unroll
    for (int i = 0; i < 32; i++) h[i] = 0ull;

    for (int t0 = 0; t0 < CH; t0 += SC_TS) {
        // staging: float4 vector loads (rows are 64 contiguous aligned floats)
#pragma unroll
        for (int j = tid; j < SC_TS * (DS_SZ / 4); j += 128) {
            const int st = j >> 4, s4 = (j & 15) * 4;
            const size_t rr = (size_t)(rbase + t0 + st);
            *(float4*)&sAb[st][s4] = *(const float4*)&abar[rr * DS_SZ + s4];
            *(float4*)&sBd[st][s4] = *(const float4*)&bd[rr * DS_SZ + s4];
        }
#pragma unroll
        for (int st = 0; st < SC_TS; st++) {
            const size_t rr = (size_t)(rbase + t0 + st);
            sx[st][tid] = __half2float(xc2[rr * (2 * DI_SZ) + dg])
                        + __half2float(xc2[rr * (2 * DI_SZ) + DI_SZ + dg]);
        }
        __syncthreads();

#pragma unroll
        for (int st = 0; st < SC_TS; st++) {
            const u64 xv2 = x2pack(sx[st][tid]);
#pragma unroll
            for (int i = 0; i < 16; i++) {
                const ulonglong2 ab = *(const ulonglong2*)&sAb[st][i * 4];
                const ulonglong2 bb = *(const ulonglong2*)&sBd[st][i * 4];
                h[2 * i]     = x2fma(ab.x, h[2 * i],     x2mul(xv2, bb.x));
                h[2 * i + 1] = x2fma(ab.y, h[2 * i + 1], x2mul(xv2, bb.y));
            }
        }
        __syncthreads();
    }

    const size_t base = ((size_t)(b * NC + k) * DS_SZ) * DI_SZ + dg;
#pragma unroll
    for (int i = 0; i < 32; i++) {
        const float2 f = x2unpack(h[i]);
        hend[base + (size_t)(2 * i) * DI_SZ] = f.x;
        hend[base + (size_t)(2 * i + 1) * DI_SZ] = f.y;
    }
}

// ---------------- pass2: sequential recombine over chunks (x4 vector) --------
__global__ void combine_kernel(const float* __restrict__ hend,
                               const float* __restrict__ pend,
                               float* __restrict__ hinit)
{
    const int idx = blockIdx.x * blockDim.x + threadIdx.x;   // B * DS * DI / 4
    if (idx >= B_SZ * DS_SZ * DI_SZ / 4) return;
    const int b = idx / (DS_SZ * DI_SZ / 4);
    const int rem4 = idx % (DS_SZ * DI_SZ / 4);
    const int s = rem4 / (DI_SZ / 4);
    const size_t rem = (size_t)rem4 * 4;

    float4 v = make_float4(0.f, 0.f, 0.f, 0.f);
#pragma unroll
    for (int k = 0; k < NC; k++) {
        const size_t off = (size_t)(b * NC + k) * DS_SZ * DI_SZ + rem;
        *(float4*)&hinit[off] = v;
        if (k + 1 < NC) {
            const float p = pend[(b * NC + k) * DS_SZ + s];
            const float4 he = *(const float4*)&hend[off];
            v.x = fmaf(p, v.x, he.x);
            v.y = fmaf(p, v.y, he.y);
            v.z = fmaf(p, v.z, he.z);
            v.w = fmaf(p, v.w, he.w);
        }
    }
}

// ------ pass3: full scan from hinit, fused gating + fp16 split output --------
__global__ __launch_bounds__(128, 4) void scan_pass2(const float* __restrict__ ssm,
                                                     const float* __restrict__ bd,
                                                     const __half* __restrict__ xc2,
                                                     const float* __restrict__ xz,
                                                     const float* __restrict__ abar,
                                                     const float* __restrict__ hinit,
                                                     const float* __restrict__ Dvec,
                                                     __half* __restrict__ y2)
{
    __shared__ __align__(16) float sAb[SC_TS][DS_SZ];
    __shared__ __align__(16) float sBd[SC_TS][DS_SZ];
    __shared__ __align__(16) float sC [SC_TS][DS_SZ];
    __shared__ float sx[SC_TS][128];
    __shared__ float sz[SC_TS][128];

    const int tid = threadIdx.x;
    const int bid = blockIdx.x;                 // B * NC * (DI/128)
    const int b  = bid / (NC * (DI_SZ / 128));
    const int r  = bid % (NC * (DI_SZ / 128));
    const int k  = r / (DI_SZ / 128);
    const int d0 = (r % (DI_SZ / 128)) * 128;
    const int rbase = b * L_SZ + k * CH;
    const int dg = d0 + tid;
    const float Dv = Dvec[dg];

    u64 h[32];
    {
        const size_t hb = ((size_t)(b * NC + k) * DS_SZ) * DI_SZ + dg;
#pragma unroll
        for (int i = 0; i < 32; i++)
            h[i] = x2pack2(hinit[hb + (size_t)(2 * i) * DI_SZ],
                           hinit[hb + (size_t)(2 * i + 1) * DI_SZ]);
    }

    for (int t0 = 0; t0 < CH; t0 += SC_TS) {
        // staging: float4 vector loads
#pragma unroll
        for (int j = tid; j < SC_TS * (DS_SZ / 4); j += 128) {
            const int st = j >> 4, s4 = (j & 15) * 4;
            const size_t rr = (size_t)(rbase + t0 + st);
            *(float4*)&sAb[st][s4] = *(const float4*)&abar[rr * DS_SZ + s4];
            *(float4*)&sBd[st][s4] = *(const float4*)&bd[rr * DS_SZ + s4];
            *(float4*)&sC [st][s4] = *(const float4*)&ssm[rr * 128 + 64 + s4];
        }
#pragma unroll
        for (int st = 0; st < SC_TS; st++) {
            const size_t rr = (size_t)(rbase + t0 + st);
            sx[st][tid] = __half2float(xc2[rr * (2 * DI_SZ) + dg])
                        + __half2float(xc2[rr * (2 * DI_SZ) + DI_SZ + dg]);
            sz[st][tid] = xz[rr * E_SZ + DI_SZ + dg];
        }
        __syncthreads();

#pragma unroll
        for (int st = 0; st < SC_TS; st++) {
            const float xv = sx[st][tid];
            const u64 xv2 = x2pack(xv);
            u64 y0 = 0ull, y1 = 0ull;
#pragma unroll
            for (int i = 0; i < 16; i++) {
                const ulonglong2 ab = *(const ulonglong2*)&sAb[st][i * 4];
                const ulonglong2 bb = *(const ulonglong2*)&sBd[st][i * 4];
                const ulonglong2 cc = *(const ulonglong2*)&sC [st][i * 4];
                h[2 * i]     = x2fma(ab.x, h[2 * i],     x2mul(xv2, bb.x));
                h[2 * i + 1] = x2fma(ab.y, h[2 * i + 1], x2mul(xv2, bb.y));
                y0 = x2fma(h[2 * i],     cc.x, y0);
                y1 = x2fma(h[2 * i + 1], cc.y, y1);
            }
            const float2 yf = x2unpack(x2add(y0, y1));
            const float yp = yf.x + yf.y;

            const float zv = sz[st][tid];
            const float sig = 1.f / (1.f + __expf(-zv));
            const float v = (yp + xv * Dv) * (zv * sig);

            const __half hh = __float2half_rn(v);
            const size_t gt = (size_t)(rbase + t0 + st);
            y2[gt * (2 * DI_SZ) + dg] = hh;
            y2[gt * (2 * DI_SZ) + DI_SZ + dg] = __float2half_rn(v - __half2float(hh));
        }
        __syncthreads();
    }
}

// ---------------- launch ----------------
extern "C" void kernel_launch(void* const* d_in, const int* in_sizes, int n_in,
                              void* d_out, int out_size)
{
    const float* x      = (const float*)d_in[0];
    const float* W_in   = (const float*)d_in[1];
    const float* conv_w = (const float*)d_in[2];
    const float* conv_b = (const float*)d_in[3];
    const float* W_x    = (const float*)d_in[4];
    const float* A_log  = (const float*)d_in[5];
    const float* Dvec   = (const float*)d_in[6];
    const float* W_out  = (const float*)d_in[7];
    float* out = (float*)d_out;

    float *xz, *ssm, *abar, *bd, *pend, *hend, *hinit;
    __half *x2, *Win2, *xc2, *Wx2, *y2, *Wout2;
    cudaGetSymbolAddress((void**)&xz,    g_xz);
    cudaGetSymbolAddress((void**)&ssm,   g_ssm);
    cudaGetSymbolAddress((void**)&abar,  g_abar);
    cudaGetSymbolAddress((void**)&bd,    g_bd);
    cudaGetSymbolAddress((void**)&pend,  g_pend);
    cudaGetSymbolAddress((void**)&hend,  g_hend);
    cudaGetSymbolAddress((void**)&hinit, g_hinit);
    cudaGetSymbolAddress((void**)&x2,    g_x2);
    cudaGetSymbolAddress((void**)&Win2,  g_Win2);
    cudaGetSymbolAddress((void**)&xc2,   g_xc2);
    cudaGetSymbolAddress((void**)&Wx2,   g_Wx2);
    cudaGetSymbolAddress((void**)&y2,    g_y2);
    cudaGetSymbolAddress((void**)&Wout2, g_Wout2);

    // 1) split x, W_in; GEMM1: xz = x @ W_in^T  (M=4096, N=4096, K=1024)
    split_f16_kernel<<<(T_SZ * DM_SZ / 4 + 255) / 256, 256>>>(x, x2, DM_SZ, (size_t)T_SZ * DM_SZ);
    split_f16_kernel<<<(E_SZ * DM_SZ / 4 + 255) / 256, 256>>>(W_in, Win2, DM_SZ, (size_t)E_SZ * DM_SZ);
    gemm_mma<128, 128, 32, 64, 3><<<dim3(E_SZ / 128, T_SZ / 128), 256>>>(x2, Win2, xz, DM_SZ, E_SZ);

    // 2) depthwise conv + SiLU -> xc2 (fp16 hi/lo planes only)
    conv_silu_split_kernel<<<(T_SZ * DI_SZ / 2 + 255) / 256, 256>>>(xz, conv_w, conv_b, xc2);

    // 3) split W_x[0:128]; GEMM2: ssm = xc @ Wx^T  (M=4096, N=128, K=2048)
    split_f16_kernel<<<(128 * DI_SZ / 4 + 255) / 256, 256>>>(W_x, Wx2, DI_SZ, (size_t)128 * DI_SZ);
    gemm_mma<64, 64, 32, 32, 3><<<dim3(128 / 64, T_SZ / 64), 128>>>(xc2, Wx2, ssm, DI_SZ, 128);

    // 3b) dt GEMV + softplus + abar + bd = B*dt
    dt_abar_kernel<<<T_SZ, 128>>>(xc2, W_x, A_log, ssm, abar, bd);

    // 4) chunked scan: hend (skip last chunk) -> combine -> full scan + gating
    pend_kernel<<<(B_SZ * NC * DS_SZ + 127) / 128, 128>>>(abar, pend);
    scan_pass1<<<B_SZ * (NC - 1) * (DI_SZ / 128), 128>>>(bd, xc2, abar, hend);
    combine_kernel<<<(B_SZ * DS_SZ * DI_SZ / 4 + 255) / 256, 256>>>(hend, pend, hinit);
    scan_pass2<<<B_SZ * NC * (DI_SZ / 128), 128>>>(ssm, bd, xc2, xz, abar, hinit, Dvec, y2);

    // 5) GEMM3: out = y @ W_out^T  (M=4096, N=1024, K=2048)
    split_f16_kernel<<<(DM_SZ * DI_SZ / 4 + 255) / 256, 256>>>(W_out, Wout2, DI_SZ, (size_t)DM_SZ * DI_SZ);
    gemm_mma<128, 128, 32, 64, 3><<<dim3(DM_SZ / 128, T_SZ / 128), 256>>>(y2, Wout2, out, DI_SZ, DM_SZ);
}